// round 2
// baseline (speedup 1.0000x reference)
#include <cuda_runtime.h>
#include <cuda_bf16.h>
#include <cstdint>

// ---------------------------------------------------------------------------
// Graph problem:  out[n] = (segment_sum(pred_prob[src], dst)[n] - 1)^2 * special_cost[n]
// N = 1,000,000 nodes, E = 16,000,000 edges.
// Strategy: init out to -1.0, RED-scatter pred_prob[src[e]] into out[dst[e]],
// epilogue out[n] = out[n]*out[n]*special_cost[n].
// ---------------------------------------------------------------------------

__global__ __launch_bounds__(256) void init_kernel(float* __restrict__ out, int n) {
    int i = blockIdx.x * blockDim.x + threadIdx.x;
    int base = i * 4;
    if (base + 3 < n) {
        *reinterpret_cast<float4*>(out + base) =
            make_float4(-1.0f, -1.0f, -1.0f, -1.0f);
    } else {
        for (int k = base; k < n; ++k) out[k] = -1.0f;
    }
}

__global__ __launch_bounds__(256) void scatter_kernel(
        const float* __restrict__ pred_prob,
        const int*   __restrict__ src,
        const int*   __restrict__ dst,
        float*       __restrict__ out,
        int num_edges) {
    // 4 edges per thread via int4 loads; coalesced 16B streaming reads.
    int i = blockIdx.x * blockDim.x + threadIdx.x;
    int base = i * 4;
    if (base + 3 < num_edges) {
        int4 s4 = *reinterpret_cast<const int4*>(src + base);
        int4 d4 = *reinterpret_cast<const int4*>(dst + base);
        float m0 = __ldg(pred_prob + s4.x);
        float m1 = __ldg(pred_prob + s4.y);
        float m2 = __ldg(pred_prob + s4.z);
        float m3 = __ldg(pred_prob + s4.w);
        // return value unused -> ptxas emits RED (no round-trip)
        atomicAdd(out + d4.x, m0);
        atomicAdd(out + d4.y, m1);
        atomicAdd(out + d4.z, m2);
        atomicAdd(out + d4.w, m3);
    } else {
        for (int e = base; e < num_edges; ++e) {
            atomicAdd(out + dst[e], __ldg(pred_prob + src[e]));
        }
    }
}

__global__ __launch_bounds__(256) void apply_kernel(
        float* __restrict__ out,
        const float* __restrict__ special_cost,
        int n) {
    int i = blockIdx.x * blockDim.x + threadIdx.x;
    int base = i * 4;
    if (base + 3 < n) {
        float4 h = *reinterpret_cast<const float4*>(out + base);
        float4 c = *reinterpret_cast<const float4*>(special_cost + base);
        h.x = h.x * h.x * c.x;
        h.y = h.y * h.y * c.y;
        h.z = h.z * h.z * c.z;
        h.w = h.w * h.w * c.w;
        *reinterpret_cast<float4*>(out + base) = h;
    } else {
        for (int k = base; k < n; ++k) {
            float h = out[k];
            out[k] = h * h * special_cost[k];
        }
    }
}

extern "C" void kernel_launch(void* const* d_in, const int* in_sizes, int n_in,
                              void* d_out, int out_size) {
    const float* pred_prob    = (const float*)d_in[0];
    const float* special_cost = (const float*)d_in[1];
    const int*   src          = (const int*)d_in[2];
    const int*   dst          = (const int*)d_in[3];
    float*       out          = (float*)d_out;

    const int N = in_sizes[0];   // num nodes
    const int E = in_sizes[2];   // num edges

    {
        int threads = 256;
        int work = (N + 3) / 4;
        int blocks = (work + threads - 1) / threads;
        init_kernel<<<blocks, threads>>>(out, N);
    }
    {
        int threads = 256;
        int work = (E + 3) / 4;
        int blocks = (work + threads - 1) / threads;
        scatter_kernel<<<blocks, threads>>>(pred_prob, src, dst, out, E);
    }
    {
        int threads = 256;
        int work = (N + 3) / 4;
        int blocks = (work + threads - 1) / threads;
        apply_kernel<<<blocks, threads>>>(out, special_cost, N);
    }
}